// round 7
// baseline (speedup 1.0000x reference)
#include <cuda_runtime.h>

#define NN 100000
#define EE 1600000
#define PP 200000

// Scratch (allocation-free rule: __device__ globals)
__device__ float g_h0[NN * 64];   // 2x + scatter_sum
__device__ float g_h [NN * 64];   // node embedding after MLP
__device__ float g_u [NN * 64];   // h @ (A+C)
__device__ float g_v [NN * 64];   // h @ (A+D)
__device__ float g_AC[64 * 64];
__device__ float g_AD[64 * 64];

// ---------------------------------------------------------------------------
// K0: h0 = 2*x  (vectorized)
__global__ void k_init(const float* __restrict__ x) {
    int i = blockIdx.x * blockDim.x + threadIdx.x;
    if (i < NN * 16) {
        float4 v = reinterpret_cast<const float4*>(x)[i];
        v.x += v.x; v.y += v.y; v.z += v.z; v.w += v.w;
        reinterpret_cast<float4*>(g_h0)[i] = v;
    }
}

// ---------------------------------------------------------------------------
// K1: scatter  h0[dst] += x[src]  via 16B vector reductions (no return value)
__global__ void k_scatter(const float* __restrict__ x, const int* __restrict__ ei) {
    int u = blockIdx.x * blockDim.x + threadIdx.x;
    if (u >= EE * 16) return;
    int e = u >> 4;        // edge id
    int c = u & 15;        // float4 chunk within the 64-float feature
    int src = ei[e];
    int dst = ei[EE + e];
    float4 val = reinterpret_cast<const float4*>(x)[src * 16 + c];
    float* p = &g_h0[dst * 64 + c * 4];
    asm volatile("red.global.add.v4.f32 [%0], {%1, %2, %3, %4};"
                 :: "l"(p), "f"(val.x), "f"(val.y), "f"(val.z), "f"(val.w)
                 : "memory");
}

// ---------------------------------------------------------------------------
// K2: AC = A + C, AD = A + D  (dw1 = [A;B;C;D], each 64x64, row-major [k][f])
__global__ void k_prep(const float* __restrict__ dw1) {
    int i = blockIdx.x * blockDim.x + threadIdx.x;
    if (i < 4096) {
        float a = dw1[i];                      // A block: rows 0..63
        g_AC[i] = a + dw1[128 * 64 + i];       // + C block (rows 128..191)
        g_AD[i] = a + dw1[192 * 64 + i];       // + D block (rows 192..255)
    }
}

// ---------------------------------------------------------------------------
// K3: node MLP: h = relu( relu(h0@w1 + b1) @ w2 + b2 )
// One warp per node; lane l owns output features l and l+32.
__global__ void __launch_bounds__(256) k_mlp(
    const float* __restrict__ w1, const float* __restrict__ b1,
    const float* __restrict__ w2, const float* __restrict__ b2)
{
    __shared__ float  sw1[64 * 64];
    __shared__ float  sw2[64 * 64];
    __shared__ float4 stage[8][16];
    int tid = threadIdx.x;
    for (int i = tid; i < 4096; i += 256) { sw1[i] = w1[i]; sw2[i] = w2[i]; }
    __syncthreads();

    int wid  = tid >> 5;
    int lane = tid & 31;
    int node = blockIdx.x * 8 + wid;
    if (node >= NN) return;

    float* st = reinterpret_cast<float*>(stage[wid]);
    const float* h0 = g_h0 + node * 64;
    st[lane]      = h0[lane];
    st[lane + 32] = h0[lane + 32];
    __syncwarp();

    float acc0 = b1[lane], acc1 = b1[lane + 32];
    #pragma unroll
    for (int k4 = 0; k4 < 16; k4++) {
        float4 m = stage[wid][k4];
        int k = k4 * 4;
        acc0 += m.x * sw1[(k    ) * 64 + lane]; acc1 += m.x * sw1[(k    ) * 64 + lane + 32];
        acc0 += m.y * sw1[(k + 1) * 64 + lane]; acc1 += m.y * sw1[(k + 1) * 64 + lane + 32];
        acc0 += m.z * sw1[(k + 2) * 64 + lane]; acc1 += m.z * sw1[(k + 2) * 64 + lane + 32];
        acc0 += m.w * sw1[(k + 3) * 64 + lane]; acc1 += m.w * sw1[(k + 3) * 64 + lane + 32];
    }
    acc0 = fmaxf(acc0, 0.0f); acc1 = fmaxf(acc1, 0.0f);

    __syncwarp();
    st[lane] = acc0; st[lane + 32] = acc1;
    __syncwarp();

    acc0 = b2[lane]; acc1 = b2[lane + 32];
    #pragma unroll
    for (int k4 = 0; k4 < 16; k4++) {
        float4 m = stage[wid][k4];
        int k = k4 * 4;
        acc0 += m.x * sw2[(k    ) * 64 + lane]; acc1 += m.x * sw2[(k    ) * 64 + lane + 32];
        acc0 += m.y * sw2[(k + 1) * 64 + lane]; acc1 += m.y * sw2[(k + 1) * 64 + lane + 32];
        acc0 += m.z * sw2[(k + 2) * 64 + lane]; acc1 += m.z * sw2[(k + 2) * 64 + lane + 32];
        acc0 += m.w * sw2[(k + 3) * 64 + lane]; acc1 += m.w * sw2[(k + 3) * 64 + lane + 32];
    }
    acc0 = fmaxf(acc0, 0.0f); acc1 = fmaxf(acc1, 0.0f);
    g_h[node * 64 + lane]      = acc0;
    g_h[node * 64 + lane + 32] = acc1;
}

// ---------------------------------------------------------------------------
// K4: u = h @ AC, v = h @ AD   (one warp per node, both GEMVs fused)
__global__ void __launch_bounds__(256) k_uv() {
    __shared__ float  sAC[64 * 64];
    __shared__ float  sAD[64 * 64];
    __shared__ float4 stage[8][16];
    int tid = threadIdx.x;
    for (int i = tid; i < 4096; i += 256) { sAC[i] = g_AC[i]; sAD[i] = g_AD[i]; }
    __syncthreads();

    int wid  = tid >> 5;
    int lane = tid & 31;
    int node = blockIdx.x * 8 + wid;
    if (node >= NN) return;

    float* st = reinterpret_cast<float*>(stage[wid]);
    const float* h = g_h + node * 64;
    st[lane]      = h[lane];
    st[lane + 32] = h[lane + 32];
    __syncwarp();

    float u0 = 0.f, u1 = 0.f, v0 = 0.f, v1 = 0.f;
    #pragma unroll
    for (int k4 = 0; k4 < 16; k4++) {
        float4 m = stage[wid][k4];
        int k = k4 * 4;
        u0 += m.x * sAC[(k    ) * 64 + lane]; u1 += m.x * sAC[(k    ) * 64 + lane + 32];
        v0 += m.x * sAD[(k    ) * 64 + lane]; v1 += m.x * sAD[(k    ) * 64 + lane + 32];
        u0 += m.y * sAC[(k + 1) * 64 + lane]; u1 += m.y * sAC[(k + 1) * 64 + lane + 32];
        v0 += m.y * sAD[(k + 1) * 64 + lane]; v1 += m.y * sAD[(k + 1) * 64 + lane + 32];
        u0 += m.z * sAC[(k + 2) * 64 + lane]; u1 += m.z * sAC[(k + 2) * 64 + lane + 32];
        v0 += m.z * sAD[(k + 2) * 64 + lane]; v1 += m.z * sAD[(k + 2) * 64 + lane + 32];
        u0 += m.w * sAC[(k + 3) * 64 + lane]; u1 += m.w * sAC[(k + 3) * 64 + lane + 32];
        v0 += m.w * sAD[(k + 3) * 64 + lane]; v1 += m.w * sAD[(k + 3) * 64 + lane + 32];
    }
    g_u[node * 64 + lane]      = u0;
    g_u[node * 64 + lane + 32] = u1;
    g_v[node * 64 + lane]      = v0;
    g_v[node * 64 + lane + 32] = v1;
}

// ---------------------------------------------------------------------------
// K5: per pair p = (i,j):
//   z = relu( u[i] + v[j] + db1 + (h[i] (*) h[j]) @ B )
//   out[p] = z @ dw2 + db2
__global__ void __launch_bounds__(256) k_pair(
    const int* __restrict__ idx,
    const float* __restrict__ dw1, const float* __restrict__ db1,
    const float* __restrict__ dw2, const float* __restrict__ db2,
    float* __restrict__ out)
{
    __shared__ float  sB[64 * 64];
    __shared__ float  sdw2[64];
    __shared__ float4 stage[8][16];
    int tid = threadIdx.x;
    for (int i = tid; i < 4096; i += 256) sB[i] = dw1[64 * 64 + i];  // B block
    if (tid < 64) sdw2[tid] = dw2[tid];
    __syncthreads();

    int wid  = tid >> 5;
    int lane = tid & 31;
    int p = blockIdx.x * 8 + wid;
    if (p >= PP) return;

    int i = idx[p];
    int j = idx[PP + p];
    const float* e1 = g_h + i * 64;
    const float* e2 = g_h + j * 64;

    float* st = reinterpret_cast<float*>(stage[wid]);
    st[lane]      = e1[lane]      * e2[lane];
    st[lane + 32] = e1[lane + 32] * e2[lane + 32];
    __syncwarp();

    float acc0 = g_u[i * 64 + lane]      + g_v[j * 64 + lane]      + db1[lane];
    float acc1 = g_u[i * 64 + lane + 32] + g_v[j * 64 + lane + 32] + db1[lane + 32];
    #pragma unroll
    for (int k4 = 0; k4 < 16; k4++) {
        float4 m = stage[wid][k4];
        int k = k4 * 4;
        acc0 += m.x * sB[(k    ) * 64 + lane]; acc1 += m.x * sB[(k    ) * 64 + lane + 32];
        acc0 += m.y * sB[(k + 1) * 64 + lane]; acc1 += m.y * sB[(k + 1) * 64 + lane + 32];
        acc0 += m.z * sB[(k + 2) * 64 + lane]; acc1 += m.z * sB[(k + 2) * 64 + lane + 32];
        acc0 += m.w * sB[(k + 3) * 64 + lane]; acc1 += m.w * sB[(k + 3) * 64 + lane + 32];
    }
    acc0 = fmaxf(acc0, 0.0f); acc1 = fmaxf(acc1, 0.0f);

    float r = acc0 * sdw2[lane] + acc1 * sdw2[lane + 32];
    #pragma unroll
    for (int o = 16; o > 0; o >>= 1)
        r += __shfl_down_sync(0xffffffffu, r, o);
    if (lane == 0) out[p] = r + db2[0];
}

// ---------------------------------------------------------------------------
extern "C" void kernel_launch(void* const* d_in, const int* in_sizes, int n_in,
                              void* d_out, int out_size) {
    const float* x   = (const float*)d_in[0];
    const int*   ei  = (const int*)  d_in[1];
    // d_in[2] = curvature (unused by the output)
    const int*   idx = (const int*)  d_in[3];
    const float* w1  = (const float*)d_in[4];
    const float* b1  = (const float*)d_in[5];
    const float* w2  = (const float*)d_in[6];
    const float* b2  = (const float*)d_in[7];
    const float* dw1 = (const float*)d_in[8];
    const float* db1 = (const float*)d_in[9];
    const float* dw2 = (const float*)d_in[10];
    const float* db2 = (const float*)d_in[11];
    float* out = (float*)d_out;

    k_init   <<<(NN * 16 + 255) / 256, 256>>>(x);
    k_scatter<<<(EE * 16 + 255) / 256, 256>>>(x, ei);
    k_prep   <<<16, 256>>>(dw1);
    k_mlp    <<<(NN + 7) / 8, 256>>>(w1, b1, w2, b2);
    k_uv     <<<(NN + 7) / 8, 256>>>();
    k_pair   <<<(PP + 7) / 8, 256>>>(idx, dw1, db1, dw2, db2, out);
}

// round 8
// speedup vs baseline: 1.4717x; 1.4717x over previous
#include <cuda_runtime.h>

#define NN 100000
#define EE 1600000
#define PP 200000

// Scratch (allocation-free rule: __device__ globals)
__device__ float g_h0[NN * 64];   // 2x + scatter_sum
__device__ float g_h [NN * 64];   // node embedding after MLP
__device__ float g_u [NN * 64];   // h @ (A+C)
__device__ float g_v [NN * 64];   // h @ (A+D)

// ---------------------------------------------------------------------------
// K0: h0 = 2*x  (vectorized)
__global__ void k_init(const float* __restrict__ x) {
    int i = blockIdx.x * blockDim.x + threadIdx.x;
    if (i < NN * 16) {
        float4 v = reinterpret_cast<const float4*>(x)[i];
        v.x += v.x; v.y += v.y; v.z += v.z; v.w += v.w;
        reinterpret_cast<float4*>(g_h0)[i] = v;
    }
}

// ---------------------------------------------------------------------------
// K1: scatter  h0[dst] += x[src].  One thread per edge; 16 vector reductions.
__global__ void __launch_bounds__(256) k_scatter(const float* __restrict__ x,
                                                 const int* __restrict__ ei) {
    int e = blockIdx.x * blockDim.x + threadIdx.x;
    if (e >= EE) return;
    int src = ei[e];
    int dst = ei[EE + e];
    const float4* xs = reinterpret_cast<const float4*>(x) + src * 16;
    float* hd = &g_h0[dst * 64];
    #pragma unroll
    for (int c = 0; c < 16; c++) {
        float4 val = xs[c];
        asm volatile("red.global.add.v4.f32 [%0], {%1, %2, %3, %4};"
                     :: "l"(hd + c * 4), "f"(val.x), "f"(val.y), "f"(val.z), "f"(val.w)
                     : "memory");
    }
}

// ---------------------------------------------------------------------------
// K3: node MLP, register-tiled: one warp processes 8 nodes.
// Lane l owns output features l and l+32 for all 8 nodes.
__global__ void __launch_bounds__(128) k_mlp(
    const float* __restrict__ w1, const float* __restrict__ b1,
    const float* __restrict__ w2, const float* __restrict__ b2)
{
    __shared__ float sw1[4096];
    __shared__ float sw2[4096];
    __shared__ float stage[4][8][64];
    int tid = threadIdx.x;
    for (int i = tid; i < 4096; i += 128) { sw1[i] = w1[i]; sw2[i] = w2[i]; }

    int wid  = tid >> 5;
    int lane = tid & 31;
    int base = blockIdx.x * 32 + wid * 8;

    // stage h0 for 8 nodes
    #pragma unroll
    for (int t = 0; t < 8; t++) {
        int node = base + t;
        if (node < NN) {
            stage[wid][t][lane]      = g_h0[node * 64 + lane];
            stage[wid][t][lane + 32] = g_h0[node * 64 + lane + 32];
        }
    }
    __syncthreads();

    float bb0 = b1[lane], bb1 = b1[lane + 32];
    float a0[8], a1[8];
    #pragma unroll
    for (int t = 0; t < 8; t++) { a0[t] = bb0; a1[t] = bb1; }

    // ---- layer 1 ----
    #pragma unroll
    for (int k4 = 0; k4 < 16; k4++) {
        float4 m[8];
        #pragma unroll
        for (int t = 0; t < 8; t++)
            m[t] = *reinterpret_cast<const float4*>(&stage[wid][t][k4 * 4]);
        #pragma unroll
        for (int kk = 0; kk < 4; kk++) {
            int k = k4 * 4 + kk;
            float w0  = sw1[k * 64 + lane];
            float w1v = sw1[k * 64 + lane + 32];
            #pragma unroll
            for (int t = 0; t < 8; t++) {
                float mv = (kk == 0) ? m[t].x : (kk == 1) ? m[t].y : (kk == 2) ? m[t].z : m[t].w;
                a0[t] = fmaf(mv, w0,  a0[t]);
                a1[t] = fmaf(mv, w1v, a1[t]);
            }
        }
    }
    __syncwarp();
    #pragma unroll
    for (int t = 0; t < 8; t++) {
        stage[wid][t][lane]      = fmaxf(a0[t], 0.0f);
        stage[wid][t][lane + 32] = fmaxf(a1[t], 0.0f);
    }
    __syncwarp();

    bb0 = b2[lane]; bb1 = b2[lane + 32];
    #pragma unroll
    for (int t = 0; t < 8; t++) { a0[t] = bb0; a1[t] = bb1; }

    // ---- layer 2 ----
    #pragma unroll
    for (int k4 = 0; k4 < 16; k4++) {
        float4 m[8];
        #pragma unroll
        for (int t = 0; t < 8; t++)
            m[t] = *reinterpret_cast<const float4*>(&stage[wid][t][k4 * 4]);
        #pragma unroll
        for (int kk = 0; kk < 4; kk++) {
            int k = k4 * 4 + kk;
            float w0  = sw2[k * 64 + lane];
            float w1v = sw2[k * 64 + lane + 32];
            #pragma unroll
            for (int t = 0; t < 8; t++) {
                float mv = (kk == 0) ? m[t].x : (kk == 1) ? m[t].y : (kk == 2) ? m[t].z : m[t].w;
                a0[t] = fmaf(mv, w0,  a0[t]);
                a1[t] = fmaf(mv, w1v, a1[t]);
            }
        }
    }
    #pragma unroll
    for (int t = 0; t < 8; t++) {
        int node = base + t;
        if (node < NN) {
            g_h[node * 64 + lane]      = fmaxf(a0[t], 0.0f);
            g_h[node * 64 + lane + 32] = fmaxf(a1[t], 0.0f);
        }
    }
}

// ---------------------------------------------------------------------------
// K4: u = h @ (A+C), v = h @ (A+D).  Register-tiled, 8 nodes/warp, both fused.
__global__ void __launch_bounds__(128) k_uv(const float* __restrict__ dw1) {
    __shared__ float sAC[4096];
    __shared__ float sAD[4096];
    __shared__ float stage[4][8][64];
    int tid = threadIdx.x;
    for (int i = tid; i < 4096; i += 128) {
        float a = dw1[i];                       // A block (rows 0..63)
        sAC[i] = a + dw1[128 * 64 + i];         // + C (rows 128..191)
        sAD[i] = a + dw1[192 * 64 + i];         // + D (rows 192..255)
    }

    int wid  = tid >> 5;
    int lane = tid & 31;
    int base = blockIdx.x * 32 + wid * 8;

    #pragma unroll
    for (int t = 0; t < 8; t++) {
        int node = base + t;
        if (node < NN) {
            stage[wid][t][lane]      = g_h[node * 64 + lane];
            stage[wid][t][lane + 32] = g_h[node * 64 + lane + 32];
        }
    }
    __syncthreads();

    float u0[8], u1[8], v0[8], v1[8];
    #pragma unroll
    for (int t = 0; t < 8; t++) { u0[t] = u1[t] = v0[t] = v1[t] = 0.0f; }

    #pragma unroll
    for (int k4 = 0; k4 < 16; k4++) {
        float4 m[8];
        #pragma unroll
        for (int t = 0; t < 8; t++)
            m[t] = *reinterpret_cast<const float4*>(&stage[wid][t][k4 * 4]);
        #pragma unroll
        for (int kk = 0; kk < 4; kk++) {
            int k = k4 * 4 + kk;
            float c0 = sAC[k * 64 + lane];
            float c1 = sAC[k * 64 + lane + 32];
            float d0 = sAD[k * 64 + lane];
            float d1 = sAD[k * 64 + lane + 32];
            #pragma unroll
            for (int t = 0; t < 8; t++) {
                float mv = (kk == 0) ? m[t].x : (kk == 1) ? m[t].y : (kk == 2) ? m[t].z : m[t].w;
                u0[t] = fmaf(mv, c0, u0[t]);
                u1[t] = fmaf(mv, c1, u1[t]);
                v0[t] = fmaf(mv, d0, v0[t]);
                v1[t] = fmaf(mv, d1, v1[t]);
            }
        }
    }
    #pragma unroll
    for (int t = 0; t < 8; t++) {
        int node = base + t;
        if (node < NN) {
            g_u[node * 64 + lane]      = u0[t];
            g_u[node * 64 + lane + 32] = u1[t];
            g_v[node * 64 + lane]      = v0[t];
            g_v[node * 64 + lane + 32] = v1[t];
        }
    }
}

// ---------------------------------------------------------------------------
// K5: per pair p=(i,j):
//   z = relu( u[i] + v[j] + db1 + (h[i] (*) h[j]) @ B );  out = z@dw2 + db2
// Register-tiled: 8 pairs per warp.
__global__ void __launch_bounds__(128) k_pair(
    const int* __restrict__ idx,
    const float* __restrict__ dw1, const float* __restrict__ db1,
    const float* __restrict__ dw2, const float* __restrict__ db2,
    float* __restrict__ out)
{
    __shared__ float sB[4096];
    __shared__ float stage[4][8][64];
    int tid = threadIdx.x;
    for (int i = tid; i < 4096; i += 128) sB[i] = dw1[64 * 64 + i];  // B block

    int wid  = tid >> 5;
    int lane = tid & 31;
    int base = blockIdx.x * 32 + wid * 8;

    float a0[8], a1[8];
    float bb0 = db1[lane], bb1 = db1[lane + 32];

    #pragma unroll
    for (int t = 0; t < 8; t++) {
        int p = base + t;
        if (p < PP) {
            int i = idx[p];
            int j = idx[PP + p];
            stage[wid][t][lane]      = g_h[i * 64 + lane]      * g_h[j * 64 + lane];
            stage[wid][t][lane + 32] = g_h[i * 64 + lane + 32] * g_h[j * 64 + lane + 32];
            a0[t] = g_u[i * 64 + lane]      + g_v[j * 64 + lane]      + bb0;
            a1[t] = g_u[i * 64 + lane + 32] + g_v[j * 64 + lane + 32] + bb1;
        } else { a0[t] = a1[t] = 0.0f; }
    }
    __syncthreads();

    #pragma unroll
    for (int k4 = 0; k4 < 16; k4++) {
        float4 m[8];
        #pragma unroll
        for (int t = 0; t < 8; t++)
            m[t] = *reinterpret_cast<const float4*>(&stage[wid][t][k4 * 4]);
        #pragma unroll
        for (int kk = 0; kk < 4; kk++) {
            int k = k4 * 4 + kk;
            float w0  = sB[k * 64 + lane];
            float w1v = sB[k * 64 + lane + 32];
            #pragma unroll
            for (int t = 0; t < 8; t++) {
                float mv = (kk == 0) ? m[t].x : (kk == 1) ? m[t].y : (kk == 2) ? m[t].z : m[t].w;
                a0[t] = fmaf(mv, w0,  a0[t]);
                a1[t] = fmaf(mv, w1v, a1[t]);
            }
        }
    }

    float dwa = dw2[lane], dwb = dw2[lane + 32];
    float bout = db2[0];
    #pragma unroll
    for (int t = 0; t < 8; t++) {
        float r = fmaxf(a0[t], 0.0f) * dwa + fmaxf(a1[t], 0.0f) * dwb;
        #pragma unroll
        for (int o = 16; o > 0; o >>= 1)
            r += __shfl_down_sync(0xffffffffu, r, o);
        int p = base + t;
        if (lane == 0 && p < PP) out[p] = r + bout;
    }
}

// ---------------------------------------------------------------------------
extern "C" void kernel_launch(void* const* d_in, const int* in_sizes, int n_in,
                              void* d_out, int out_size) {
    const float* x   = (const float*)d_in[0];
    const int*   ei  = (const int*)  d_in[1];
    // d_in[2] = curvature (unused by the output)
    const int*   idx = (const int*)  d_in[3];
    const float* w1  = (const float*)d_in[4];
    const float* b1  = (const float*)d_in[5];
    const float* w2  = (const float*)d_in[6];
    const float* b2  = (const float*)d_in[7];
    const float* dw1 = (const float*)d_in[8];
    const float* db1 = (const float*)d_in[9];
    const float* dw2 = (const float*)d_in[10];
    const float* db2 = (const float*)d_in[11];
    float* out = (float*)d_out;

    k_init   <<<(NN * 16 + 255) / 256, 256>>>(x);
    k_scatter<<<(EE + 255) / 256, 256>>>(x, ei);
    k_mlp    <<<(NN + 31) / 32, 128>>>(w1, b1, w2, b2);
    k_uv     <<<(NN + 31) / 32, 128>>>(dw1);
    k_pair   <<<(PP + 31) / 32, 128>>>(idx, dw1, db1, dw2, db2, out);
}

// round 9
// speedup vs baseline: 2.0515x; 1.3940x over previous
#include <cuda_runtime.h>

#define NN 100000
#define EE 1600000
#define PP 200000

// Scratch (allocation-free rule: __device__ globals)
__device__ float g_h0[NN * 64];   // 2x + scatter_sum
__device__ float g_h [NN * 64];   // node embedding after MLP
__device__ float g_u [NN * 64];   // h @ (A+C)
__device__ float g_v [NN * 64];   // h @ (A+D)

// ---------------------------------------------------------------------------
// K0: h0 = 2*x  (vectorized)
__global__ void k_init(const float* __restrict__ x) {
    int i = blockIdx.x * blockDim.x + threadIdx.x;
    if (i < NN * 16) {
        float4 v = reinterpret_cast<const float4*>(x)[i];
        v.x += v.x; v.y += v.y; v.z += v.z; v.w += v.w;
        reinterpret_cast<float4*>(g_h0)[i] = v;
    }
}

// ---------------------------------------------------------------------------
// K1: scatter  h0[dst] += x[src].
// 16 lanes per edge (one float4 chunk per lane) -> coalesced 256B row
// accesses: a warp's gather/reduce touches 2 contiguous rows (4 lines)
// instead of 32 scattered ones.
__global__ void __launch_bounds__(256) k_scatter(const float* __restrict__ x,
                                                 const int* __restrict__ ei) {
    int u = blockIdx.x * blockDim.x + threadIdx.x;
    if (u >= EE * 16) return;
    int e = u >> 4;        // edge id
    int c = u & 15;        // float4 chunk within the 64-float feature
    int src = ei[e];
    int dst = ei[EE + e];
    float4 val = reinterpret_cast<const float4*>(x)[src * 16 + c];
    float* p = &g_h0[dst * 64 + c * 4];
    asm volatile("red.global.add.v4.f32 [%0], {%1, %2, %3, %4};"
                 :: "l"(p), "f"(val.x), "f"(val.y), "f"(val.z), "f"(val.w)
                 : "memory");
}

// ---------------------------------------------------------------------------
// K2: fused node MLP + decoder precompute.
//   h = relu( relu(h0@w1+b1) @ w2 + b2 )
//   u = h @ (A+C),  v = h @ (A+D)        (dw1 = [A;B;C;D])
// Register-tiled: one warp processes 8 nodes; lane l owns features l, l+32.
// SMEM buffers reused: B1 = w1 then (A+C);  B2 = w2 then (A+D).
__global__ void __launch_bounds__(128) k_mlp_uv(
    const float* __restrict__ w1, const float* __restrict__ b1,
    const float* __restrict__ w2, const float* __restrict__ b2,
    const float* __restrict__ dw1)
{
    __shared__ float B1[4096];
    __shared__ float B2[4096];
    __shared__ float stage[4][8][64];
    int tid = threadIdx.x;
    for (int i = tid; i < 4096; i += 128) { B1[i] = w1[i]; B2[i] = w2[i]; }

    int wid  = tid >> 5;
    int lane = tid & 31;
    int base = blockIdx.x * 32 + wid * 8;

    // stage h0 for 8 nodes
    #pragma unroll
    for (int t = 0; t < 8; t++) {
        int node = base + t;
        if (node < NN) {
            stage[wid][t][lane]      = g_h0[node * 64 + lane];
            stage[wid][t][lane + 32] = g_h0[node * 64 + lane + 32];
        }
    }
    __syncthreads();

    float bb0 = b1[lane], bb1 = b1[lane + 32];
    float a0[8], a1[8];
    #pragma unroll
    for (int t = 0; t < 8; t++) { a0[t] = bb0; a1[t] = bb1; }

    // ---- layer 1 (B1 = w1) ----
    #pragma unroll
    for (int k4 = 0; k4 < 16; k4++) {
        float4 m[8];
        #pragma unroll
        for (int t = 0; t < 8; t++)
            m[t] = *reinterpret_cast<const float4*>(&stage[wid][t][k4 * 4]);
        #pragma unroll
        for (int kk = 0; kk < 4; kk++) {
            int k = k4 * 4 + kk;
            float w0  = B1[k * 64 + lane];
            float w1v = B1[k * 64 + lane + 32];
            #pragma unroll
            for (int t = 0; t < 8; t++) {
                float mv = (kk == 0) ? m[t].x : (kk == 1) ? m[t].y : (kk == 2) ? m[t].z : m[t].w;
                a0[t] = fmaf(mv, w0,  a0[t]);
                a1[t] = fmaf(mv, w1v, a1[t]);
            }
        }
    }
    __syncwarp();
    #pragma unroll
    for (int t = 0; t < 8; t++) {
        stage[wid][t][lane]      = fmaxf(a0[t], 0.0f);
        stage[wid][t][lane + 32] = fmaxf(a1[t], 0.0f);
    }
    __syncwarp();

    bb0 = b2[lane]; bb1 = b2[lane + 32];
    #pragma unroll
    for (int t = 0; t < 8; t++) { a0[t] = bb0; a1[t] = bb1; }

    // ---- layer 2 (B2 = w2) ----
    #pragma unroll
    for (int k4 = 0; k4 < 16; k4++) {
        float4 m[8];
        #pragma unroll
        for (int t = 0; t < 8; t++)
            m[t] = *reinterpret_cast<const float4*>(&stage[wid][t][k4 * 4]);
        #pragma unroll
        for (int kk = 0; kk < 4; kk++) {
            int k = k4 * 4 + kk;
            float w0  = B2[k * 64 + lane];
            float w1v = B2[k * 64 + lane + 32];
            #pragma unroll
            for (int t = 0; t < 8; t++) {
                float mv = (kk == 0) ? m[t].x : (kk == 1) ? m[t].y : (kk == 2) ? m[t].z : m[t].w;
                a0[t] = fmaf(mv, w0,  a0[t]);
                a1[t] = fmaf(mv, w1v, a1[t]);
            }
        }
    }

    // h -> gmem + stage for the uv GEMVs
    #pragma unroll
    for (int t = 0; t < 8; t++) {
        a0[t] = fmaxf(a0[t], 0.0f);
        a1[t] = fmaxf(a1[t], 0.0f);
        int node = base + t;
        if (node < NN) {
            g_h[node * 64 + lane]      = a0[t];
            g_h[node * 64 + lane + 32] = a1[t];
        }
    }
    __syncthreads();                 // everyone done reading B1/B2
    #pragma unroll
    for (int t = 0; t < 8; t++) {
        stage[wid][t][lane]      = a0[t];
        stage[wid][t][lane + 32] = a1[t];
    }
    // reload: B1 = A + C, B2 = A + D
    for (int i = tid; i < 4096; i += 128) {
        float a = dw1[i];                       // A block (rows 0..63)
        B1[i] = a + dw1[128 * 64 + i];          // + C (rows 128..191)
        B2[i] = a + dw1[192 * 64 + i];          // + D (rows 192..255)
    }
    __syncthreads();

    float u0[8], u1[8], v0[8], v1[8];
    #pragma unroll
    for (int t = 0; t < 8; t++) { u0[t] = u1[t] = v0[t] = v1[t] = 0.0f; }

    #pragma unroll
    for (int k4 = 0; k4 < 16; k4++) {
        float4 m[8];
        #pragma unroll
        for (int t = 0; t < 8; t++)
            m[t] = *reinterpret_cast<const float4*>(&stage[wid][t][k4 * 4]);
        #pragma unroll
        for (int kk = 0; kk < 4; kk++) {
            int k = k4 * 4 + kk;
            float c0 = B1[k * 64 + lane];
            float c1 = B1[k * 64 + lane + 32];
            float d0 = B2[k * 64 + lane];
            float d1 = B2[k * 64 + lane + 32];
            #pragma unroll
            for (int t = 0; t < 8; t++) {
                float mv = (kk == 0) ? m[t].x : (kk == 1) ? m[t].y : (kk == 2) ? m[t].z : m[t].w;
                u0[t] = fmaf(mv, c0, u0[t]);
                u1[t] = fmaf(mv, c1, u1[t]);
                v0[t] = fmaf(mv, d0, v0[t]);
                v1[t] = fmaf(mv, d1, v1[t]);
            }
        }
    }
    #pragma unroll
    for (int t = 0; t < 8; t++) {
        int node = base + t;
        if (node < NN) {
            g_u[node * 64 + lane]      = u0[t];
            g_u[node * 64 + lane + 32] = u1[t];
            g_v[node * 64 + lane]      = v0[t];
            g_v[node * 64 + lane + 32] = v1[t];
        }
    }
}

// ---------------------------------------------------------------------------
// K3: per pair p=(i,j):
//   z = relu( u[i] + v[j] + db1 + (h[i] (*) h[j]) @ B );  out = z@dw2 + db2
// Register-tiled: 8 pairs per warp.
__global__ void __launch_bounds__(128) k_pair(
    const int* __restrict__ idx,
    const float* __restrict__ dw1, const float* __restrict__ db1,
    const float* __restrict__ dw2, const float* __restrict__ db2,
    float* __restrict__ out)
{
    __shared__ float sB[4096];
    __shared__ float stage[4][8][64];
    int tid = threadIdx.x;
    for (int i = tid; i < 4096; i += 128) sB[i] = dw1[64 * 64 + i];  // B block

    int wid  = tid >> 5;
    int lane = tid & 31;
    int base = blockIdx.x * 32 + wid * 8;

    float a0[8], a1[8];
    float bb0 = db1[lane], bb1 = db1[lane + 32];

    #pragma unroll
    for (int t = 0; t < 8; t++) {
        int p = base + t;
        if (p < PP) {
            int i = idx[p];
            int j = idx[PP + p];
            stage[wid][t][lane]      = g_h[i * 64 + lane]      * g_h[j * 64 + lane];
            stage[wid][t][lane + 32] = g_h[i * 64 + lane + 32] * g_h[j * 64 + lane + 32];
            a0[t] = g_u[i * 64 + lane]      + g_v[j * 64 + lane]      + bb0;
            a1[t] = g_u[i * 64 + lane + 32] + g_v[j * 64 + lane + 32] + bb1;
        } else { a0[t] = a1[t] = 0.0f; }
    }
    __syncthreads();

    #pragma unroll
    for (int k4 = 0; k4 < 16; k4++) {
        float4 m[8];
        #pragma unroll
        for (int t = 0; t < 8; t++)
            m[t] = *reinterpret_cast<const float4*>(&stage[wid][t][k4 * 4]);
        #pragma unroll
        for (int kk = 0; kk < 4; kk++) {
            int k = k4 * 4 + kk;
            float w0  = sB[k * 64 + lane];
            float w1v = sB[k * 64 + lane + 32];
            #pragma unroll
            for (int t = 0; t < 8; t++) {
                float mv = (kk == 0) ? m[t].x : (kk == 1) ? m[t].y : (kk == 2) ? m[t].z : m[t].w;
                a0[t] = fmaf(mv, w0,  a0[t]);
                a1[t] = fmaf(mv, w1v, a1[t]);
            }
        }
    }

    float dwa = dw2[lane], dwb = dw2[lane + 32];
    float bout = db2[0];
    #pragma unroll
    for (int t = 0; t < 8; t++) {
        float r = fmaxf(a0[t], 0.0f) * dwa + fmaxf(a1[t], 0.0f) * dwb;
        #pragma unroll
        for (int o = 16; o > 0; o >>= 1)
            r += __shfl_down_sync(0xffffffffu, r, o);
        int p = base + t;
        if (lane == 0 && p < PP) out[p] = r + bout;
    }
}

// ---------------------------------------------------------------------------
extern "C" void kernel_launch(void* const* d_in, const int* in_sizes, int n_in,
                              void* d_out, int out_size) {
    const float* x   = (const float*)d_in[0];
    const int*   ei  = (const int*)  d_in[1];
    // d_in[2] = curvature (unused by the output)
    const int*   idx = (const int*)  d_in[3];
    const float* w1  = (const float*)d_in[4];
    const float* b1  = (const float*)d_in[5];
    const float* w2  = (const float*)d_in[6];
    const float* b2  = (const float*)d_in[7];
    const float* dw1 = (const float*)d_in[8];
    const float* db1 = (const float*)d_in[9];
    const float* dw2 = (const float*)d_in[10];
    const float* db2 = (const float*)d_in[11];
    float* out = (float*)d_out;

    k_init   <<<(NN * 16 + 255) / 256, 256>>>(x);
    k_scatter<<<(EE * 16 + 255) / 256, 256>>>(x, ei);
    k_mlp_uv <<<(NN + 31) / 32, 128>>>(w1, b1, w2, b2, dw1);
    k_pair   <<<(PP + 31) / 32, 128>>>(idx, dw1, db1, dw2, db2, out);
}

// round 10
// speedup vs baseline: 2.1643x; 1.0550x over previous
#include <cuda_runtime.h>

#define NN 100000
#define EE 1600000
#define PP 200000

// Scratch (allocation-free rule: __device__ globals)
__device__ float g_h0[NN * 64];   // 2x + scatter_sum
__device__ float g_h [NN * 64];   // node embedding after MLP
__device__ float g_u [NN * 64];   // h @ (A+C)
__device__ float g_v [NN * 64];   // h @ (A+D)

// ---------------------------------------------------------------------------
// K0: h0 = 2*x  (vectorized)
__global__ void k_init(const float* __restrict__ x) {
    int i = blockIdx.x * blockDim.x + threadIdx.x;
    if (i < NN * 16) {
        float4 v = reinterpret_cast<const float4*>(x)[i];
        v.x += v.x; v.y += v.y; v.z += v.z; v.w += v.w;
        reinterpret_cast<float4*>(g_h0)[i] = v;
    }
}

// ---------------------------------------------------------------------------
// K1: scatter  h0[dst] += x[src].  16 lanes per edge (one float4 chunk each).
__global__ void __launch_bounds__(256) k_scatter(const float* __restrict__ x,
                                                 const int* __restrict__ ei) {
    int u = blockIdx.x * blockDim.x + threadIdx.x;
    if (u >= EE * 16) return;
    int e = u >> 4;        // edge id
    int c = u & 15;        // float4 chunk within the 64-float feature
    int src = ei[e];
    int dst = ei[EE + e];
    float4 val = reinterpret_cast<const float4*>(x)[src * 16 + c];
    float* p = &g_h0[dst * 64 + c * 4];
    asm volatile("red.global.add.v4.f32 [%0], {%1, %2, %3, %4};"
                 :: "l"(p), "f"(val.x), "f"(val.y), "f"(val.z), "f"(val.w)
                 : "memory");
}

// ---------------------------------------------------------------------------
// Weight layout: Wq[k4*64 + out] = float4( w[4k4+0][out], w[4k4+1][out],
//                                          w[4k4+2][out], w[4k4+3][out] )
// -> one LDS.128 per (k4, out) = 4x fewer weight LDS; lanes read consecutive
//    16B slots -> conflict-free.

// K2: fused node MLP + decoder precompute.
//   h = relu( relu(h0@w1+b1) @ w2 + b2 );  u = h@(A+C);  v = h@(A+D)
// One warp processes 8 nodes; lane l owns output features l and l+32.
__global__ void __launch_bounds__(128) k_mlp_uv(
    const float* __restrict__ w1, const float* __restrict__ b1,
    const float* __restrict__ w2, const float* __restrict__ b2,
    const float* __restrict__ dw1)
{
    __shared__ float4 B1q[1024];
    __shared__ float4 B2q[1024];
    __shared__ float  stage[4][8][64];
    int tid = threadIdx.x;

    // pack w1, w2
    for (int i = tid; i < 1024; i += 128) {
        int k4 = i >> 6, out = i & 63;
        int kb = k4 * 4 * 64 + out;
        B1q[i] = make_float4(w1[kb], w1[kb + 64], w1[kb + 128], w1[kb + 192]);
        B2q[i] = make_float4(w2[kb], w2[kb + 64], w2[kb + 128], w2[kb + 192]);
    }

    int wid  = tid >> 5;
    int lane = tid & 31;
    int base = blockIdx.x * 32 + wid * 8;

    #pragma unroll
    for (int t = 0; t < 8; t++) {
        int node = base + t;
        if (node < NN) {
            stage[wid][t][lane]      = g_h0[node * 64 + lane];
            stage[wid][t][lane + 32] = g_h0[node * 64 + lane + 32];
        }
    }
    __syncthreads();

    float bb0 = b1[lane], bb1 = b1[lane + 32];
    float a0[8], a1[8];
    #pragma unroll
    for (int t = 0; t < 8; t++) { a0[t] = bb0; a1[t] = bb1; }

    // ---- layer 1 ----
    #pragma unroll
    for (int k4 = 0; k4 < 16; k4++) {
        float4 w0 = B1q[k4 * 64 + lane];
        float4 w1v = B1q[k4 * 64 + lane + 32];
        #pragma unroll
        for (int t = 0; t < 8; t++) {
            float4 m = *reinterpret_cast<const float4*>(&stage[wid][t][k4 * 4]);
            a0[t] = fmaf(m.x, w0.x, a0[t]);  a1[t] = fmaf(m.x, w1v.x, a1[t]);
            a0[t] = fmaf(m.y, w0.y, a0[t]);  a1[t] = fmaf(m.y, w1v.y, a1[t]);
            a0[t] = fmaf(m.z, w0.z, a0[t]);  a1[t] = fmaf(m.z, w1v.z, a1[t]);
            a0[t] = fmaf(m.w, w0.w, a0[t]);  a1[t] = fmaf(m.w, w1v.w, a1[t]);
        }
    }
    __syncwarp();
    #pragma unroll
    for (int t = 0; t < 8; t++) {
        stage[wid][t][lane]      = fmaxf(a0[t], 0.0f);
        stage[wid][t][lane + 32] = fmaxf(a1[t], 0.0f);
    }
    __syncwarp();

    bb0 = b2[lane]; bb1 = b2[lane + 32];
    #pragma unroll
    for (int t = 0; t < 8; t++) { a0[t] = bb0; a1[t] = bb1; }

    // ---- layer 2 ----
    #pragma unroll
    for (int k4 = 0; k4 < 16; k4++) {
        float4 w0 = B2q[k4 * 64 + lane];
        float4 w1v = B2q[k4 * 64 + lane + 32];
        #pragma unroll
        for (int t = 0; t < 8; t++) {
            float4 m = *reinterpret_cast<const float4*>(&stage[wid][t][k4 * 4]);
            a0[t] = fmaf(m.x, w0.x, a0[t]);  a1[t] = fmaf(m.x, w1v.x, a1[t]);
            a0[t] = fmaf(m.y, w0.y, a0[t]);  a1[t] = fmaf(m.y, w1v.y, a1[t]);
            a0[t] = fmaf(m.z, w0.z, a0[t]);  a1[t] = fmaf(m.z, w1v.z, a1[t]);
            a0[t] = fmaf(m.w, w0.w, a0[t]);  a1[t] = fmaf(m.w, w1v.w, a1[t]);
        }
    }

    // h -> gmem + restage for the uv GEMVs
    #pragma unroll
    for (int t = 0; t < 8; t++) {
        a0[t] = fmaxf(a0[t], 0.0f);
        a1[t] = fmaxf(a1[t], 0.0f);
        int node = base + t;
        if (node < NN) {
            g_h[node * 64 + lane]      = a0[t];
            g_h[node * 64 + lane + 32] = a1[t];
        }
    }
    __syncthreads();                 // everyone done reading B1q/B2q
    #pragma unroll
    for (int t = 0; t < 8; t++) {
        stage[wid][t][lane]      = a0[t];
        stage[wid][t][lane + 32] = a1[t];
    }
    // repack: B1q = pack(A + C), B2q = pack(A + D)
    for (int i = tid; i < 1024; i += 128) {
        int k4 = i >> 6, out = i & 63;
        int kb = k4 * 4 * 64 + out;
        B1q[i] = make_float4(dw1[kb]       + dw1[128 * 64 + kb],
                             dw1[kb + 64]  + dw1[128 * 64 + kb + 64],
                             dw1[kb + 128] + dw1[128 * 64 + kb + 128],
                             dw1[kb + 192] + dw1[128 * 64 + kb + 192]);
        B2q[i] = make_float4(dw1[kb]       + dw1[192 * 64 + kb],
                             dw1[kb + 64]  + dw1[192 * 64 + kb + 64],
                             dw1[kb + 128] + dw1[192 * 64 + kb + 128],
                             dw1[kb + 192] + dw1[192 * 64 + kb + 192]);
    }
    __syncthreads();

    float u0[8], u1[8], v0[8], v1[8];
    #pragma unroll
    for (int t = 0; t < 8; t++) { u0[t] = u1[t] = v0[t] = v1[t] = 0.0f; }

    #pragma unroll
    for (int k4 = 0; k4 < 16; k4++) {
        float4 c0 = B1q[k4 * 64 + lane];
        float4 c1 = B1q[k4 * 64 + lane + 32];
        float4 d0 = B2q[k4 * 64 + lane];
        float4 d1 = B2q[k4 * 64 + lane + 32];
        #pragma unroll
        for (int t = 0; t < 8; t++) {
            float4 m = *reinterpret_cast<const float4*>(&stage[wid][t][k4 * 4]);
            u0[t] = fmaf(m.x, c0.x, u0[t]);  u1[t] = fmaf(m.x, c1.x, u1[t]);
            v0[t] = fmaf(m.x, d0.x, v0[t]);  v1[t] = fmaf(m.x, d1.x, v1[t]);
            u0[t] = fmaf(m.y, c0.y, u0[t]);  u1[t] = fmaf(m.y, c1.y, u1[t]);
            v0[t] = fmaf(m.y, d0.y, v0[t]);  v1[t] = fmaf(m.y, d1.y, v1[t]);
            u0[t] = fmaf(m.z, c0.z, u0[t]);  u1[t] = fmaf(m.z, c1.z, u1[t]);
            v0[t] = fmaf(m.z, d0.z, v0[t]);  v1[t] = fmaf(m.z, d1.z, v1[t]);
            u0[t] = fmaf(m.w, c0.w, u0[t]);  u1[t] = fmaf(m.w, c1.w, u1[t]);
            v0[t] = fmaf(m.w, d0.w, v0[t]);  v1[t] = fmaf(m.w, d1.w, v1[t]);
        }
    }
    #pragma unroll
    for (int t = 0; t < 8; t++) {
        int node = base + t;
        if (node < NN) {
            g_u[node * 64 + lane]      = u0[t];
            g_u[node * 64 + lane + 32] = u1[t];
            g_v[node * 64 + lane]      = v0[t];
            g_v[node * 64 + lane + 32] = v1[t];
        }
    }
}

// ---------------------------------------------------------------------------
// K3: per pair p=(i,j):
//   z = relu( u[i] + v[j] + db1 + (h[i] (*) h[j]) @ B );  out = z@dw2 + db2
// 8 pairs per warp, 256 threads/block.
__global__ void __launch_bounds__(256) k_pair(
    const int* __restrict__ idx,
    const float* __restrict__ dw1, const float* __restrict__ db1,
    const float* __restrict__ dw2, const float* __restrict__ db2,
    float* __restrict__ out)
{
    __shared__ float4 Bq[1024];
    __shared__ float  stage[8][8][64];
    int tid = threadIdx.x;
    for (int i = tid; i < 1024; i += 256) {       // pack B block of dw1
        int k4 = i >> 6, outc = i & 63;
        int kb = 64 * 64 + k4 * 4 * 64 + outc;
        Bq[i] = make_float4(dw1[kb], dw1[kb + 64], dw1[kb + 128], dw1[kb + 192]);
    }

    int wid  = tid >> 5;
    int lane = tid & 31;
    int base = blockIdx.x * 64 + wid * 8;

    float a0[8], a1[8];
    float bb0 = db1[lane], bb1 = db1[lane + 32];

    #pragma unroll
    for (int t = 0; t < 8; t++) {
        int p = base + t;
        if (p < PP) {
            int i = idx[p];
            int j = idx[PP + p];
            stage[wid][t][lane]      = g_h[i * 64 + lane]      * g_h[j * 64 + lane];
            stage[wid][t][lane + 32] = g_h[i * 64 + lane + 32] * g_h[j * 64 + lane + 32];
            a0[t] = g_u[i * 64 + lane]      + g_v[j * 64 + lane]      + bb0;
            a1[t] = g_u[i * 64 + lane + 32] + g_v[j * 64 + lane + 32] + bb1;
        } else { a0[t] = a1[t] = 0.0f; }
    }
    __syncthreads();

    #pragma unroll
    for (int k4 = 0; k4 < 16; k4++) {
        float4 w0 = Bq[k4 * 64 + lane];
        float4 w1v = Bq[k4 * 64 + lane + 32];
        #pragma unroll
        for (int t = 0; t < 8; t++) {
            float4 m = *reinterpret_cast<const float4*>(&stage[wid][t][k4 * 4]);
            a0[t] = fmaf(m.x, w0.x, a0[t]);  a1[t] = fmaf(m.x, w1v.x, a1[t]);
            a0[t] = fmaf(m.y, w0.y, a0[t]);  a1[t] = fmaf(m.y, w1v.y, a1[t]);
            a0[t] = fmaf(m.z, w0.z, a0[t]);  a1[t] = fmaf(m.z, w1v.z, a1[t]);
            a0[t] = fmaf(m.w, w0.w, a0[t]);  a1[t] = fmaf(m.w, w1v.w, a1[t]);
        }
    }

    float dwa = dw2[lane], dwb = dw2[lane + 32];
    float bout = db2[0];
    #pragma unroll
    for (int t = 0; t < 8; t++) {
        float r = fmaxf(a0[t], 0.0f) * dwa + fmaxf(a1[t], 0.0f) * dwb;
        #pragma unroll
        for (int o = 16; o > 0; o >>= 1)
            r += __shfl_down_sync(0xffffffffu, r, o);
        int p = base + t;
        if (lane == 0 && p < PP) out[p] = r + bout;
    }
}

// ---------------------------------------------------------------------------
extern "C" void kernel_launch(void* const* d_in, const int* in_sizes, int n_in,
                              void* d_out, int out_size) {
    const float* x   = (const float*)d_in[0];
    const int*   ei  = (const int*)  d_in[1];
    // d_in[2] = curvature (unused by the output)
    const int*   idx = (const int*)  d_in[3];
    const float* w1  = (const float*)d_in[4];
    const float* b1  = (const float*)d_in[5];
    const float* w2  = (const float*)d_in[6];
    const float* b2  = (const float*)d_in[7];
    const float* dw1 = (const float*)d_in[8];
    const float* db1 = (const float*)d_in[9];
    const float* dw2 = (const float*)d_in[10];
    const float* db2 = (const float*)d_in[11];
    float* out = (float*)d_out;

    k_init   <<<(NN * 16 + 255) / 256, 256>>>(x);
    k_scatter<<<(EE * 16 + 255) / 256, 256>>>(x, ei);
    k_mlp_uv <<<(NN + 31) / 32, 128>>>(w1, b1, w2, b2, dw1);
    k_pair   <<<(PP + 63) / 64, 256>>>(idx, dw1, db1, dw2, db2, out);
}